// round 11
// baseline (speedup 1.0000x reference)
#include <cuda_runtime.h>
#include <math_constants.h>

#define NROWS 65536
#define DDIM  256
#define KCB   1024
#define NCB   3

#define BM 64
#define BN 512
#define BK 32
#define NTHREADS 256
#define CBS_TILE (BK * BN)   // 16384 floats per buffer

// ---------------- scratch (no allocations allowed) ----------------
__device__ float  g_res[(size_t)NROWS * DDIM];   // residual between stages (64 MB)
__device__ float  g_c2[NCB * KCB];               // per-stage ||c_k||^2
__device__ double g_loss[NCB];                   // per-stage sum of (code - r)^2

// ---------------- packed f32x2 helpers (sm_103a FFMA2 path) ----------------
#define FMA2(acc, a, b) \
    asm("fma.rn.f32x2 %0, %1, %2, %0;" : "+l"(acc) : "l"(a), "l"(b))
#define PACK2(out, lo, hi) \
    asm("mov.b64 %0, {%1, %2};" : "=l"(out) : "r"(__float_as_uint(lo)), "r"(__float_as_uint(hi)))
#define UNPACK2(lo, hi, in) \
    asm("mov.b64 {%0, %1}, %2;" : "=r"(lo), "=r"(hi) : "l"(in))
// 128-bit smem load directly into two packed f32x2 regs: (k,k+1),(k+2,k+3)
#define LDS_PAIR2(p0, p1, addr) \
    asm("ld.shared.v2.u64 {%0, %1}, [%2];" : "=l"(p0), "=l"(p1) : "r"(addr))

// ---------------- smem layout (floats) ----------------
// zT   : [256][68]      transposed z tile (d-major, local row index)
// cbs  : [2][32][512]   ping-pong codebook sub-tiles, d-major cbs[b][d][k]
// c2sh : [1024]
// l2s  : [64]
// redS : [64][33], redI : [64][33]
// bidx : [64]
#define ZT_STRIDE 68
#define OFF_ZT    0
#define OFF_CBS   (OFF_ZT   + 256 * ZT_STRIDE)        // 17408
#define OFF_C2    (OFF_CBS  + 2 * CBS_TILE)           // 50176
#define OFF_L2    (OFF_C2   + 1024)                   // 51200
#define OFF_REDS  (OFF_L2   + 64)                     // 51264
#define OFF_REDI  (OFF_REDS + 64 * 33)                // 53376
#define OFF_BIDX  (OFF_REDI + 64 * 33)                // 55488
#define SMEM_FLOATS (OFF_BIDX + 64)                   // 55552
#define SMEM_BYTES  (SMEM_FLOATS * 4)                 // 222208 -> 1 block/SM

// ---------------- init: zero loss accumulators, compute c2 ----------------
__global__ void rvq_init_kernel(const float* __restrict__ cb,
                                float* __restrict__ c2out,
                                double* __restrict__ loss)
{
    if (blockIdx.x == 0 && threadIdx.x < NCB) loss[threadIdx.x] = 0.0;

    int gw   = (blockIdx.x * blockDim.x + threadIdx.x) >> 5;  // one warp per codeword
    int lane = threadIdx.x & 31;
    if (gw < NCB * KCB) {
        const float* row = cb + (size_t)gw * DDIM;
        float s = 0.f;
        for (int d = lane; d < DDIM; d += 32) { float v = row[d]; s = fmaf(v, v, s); }
        #pragma unroll
        for (int o = 16; o; o >>= 1) s += __shfl_xor_sync(0xffffffffu, s, o);
        if (lane == 0) c2out[gw] = s;
    }
}

// ---------------- fused stage: GEMM + argmin + gather/update/loss ----------------
__global__ __launch_bounds__(NTHREADS, 1)
void rvq_stage_kernel(const float* __restrict__ zin,   // residual input [N,D]
                      const float* __restrict__ cbg,   // codebook (stage offset applied) [K,D]
                      const float* __restrict__ c2g,   // stage c2 [K]
                      float* __restrict__ fq,          // output quantized [N,D]
                      float* __restrict__ rout,        // residual output [N,D]
                      double* __restrict__ lossp,      // stage loss accumulator
                      int firstStage, int writeR)
{
    extern __shared__ float sm[];
    float* zT   = sm + OFF_ZT;
    float* cbs  = sm + OFF_CBS;
    float* c2sh = sm + OFF_C2;
    float* l2s  = sm + OFF_L2;
    float* redS = sm + OFF_REDS;
    int*   redI = (int*)(sm + OFF_REDI);
    int*   bidx = (int*)(sm + OFF_BIDX);

    const unsigned int smb = (unsigned int)__cvta_generic_to_shared(sm);

    const int tid = threadIdx.x;
    const int m0  = blockIdx.x * BM;
    const int tx  = tid & 31;   // lane: k = 128*q + tx*4 + {0..3}, q = 0..3 (16 k per lane)
    const int ty  = tid >> 5;   // warp id: owns rows ty*8 .. ty*8+7

    // ---- load z tile transposed into smem (coalesced float4 reads) ----
    #pragma unroll
    for (int it = 0; it < 16; ++it) {
        int f  = tid + it * NTHREADS;          // 0..4095
        int m  = f >> 6;                       // row 0..63
        int d4 = f & 63;                       // float4 index along D
        float4 v = *(const float4*)(zin + (size_t)(m0 + m) * DDIM + d4 * 4);
        zT[(d4 * 4 + 0) * ZT_STRIDE + m] = v.x;
        zT[(d4 * 4 + 1) * ZT_STRIDE + m] = v.y;
        zT[(d4 * 4 + 2) * ZT_STRIDE + m] = v.z;
        zT[(d4 * 4 + 3) * ZT_STRIDE + m] = v.w;
    }
    // ---- stage c2 into smem ----
    #pragma unroll
    for (int i = tid; i < KCB; i += NTHREADS) c2sh[i] = c2g[i];

    // ---- preload cb tile 0 (kt=0, dt=0) into buffer 0 ----
    #pragma unroll
    for (int kk = 0; kk < 2; ++kk) {
        int krow = tid + kk * 256;
        const float* src = cbg + (size_t)krow * DDIM;   // kt=0, dt=0
        #pragma unroll
        for (int i = 0; i < 8; ++i) {
            float4 v = *(const float4*)(src + i * 4);
            int d = i * 4;
            cbs[(d + 0) * BN + krow] = v.x;
            cbs[(d + 1) * BN + krow] = v.y;
            cbs[(d + 2) * BN + krow] = v.z;
            cbs[(d + 3) * BN + krow] = v.w;
        }
    }
    __syncthreads();

    // ---- l2 per row (same sequential fp32 chain as reference) ----
    if (tid < BM) {
        float s = 0.f;
        for (int d = 0; d < DDIM; ++d) { float v = zT[d * ZT_STRIDE + tid]; s = fmaf(v, v, s); }
        l2s[tid] = s;
    }
    __syncthreads();

    // ---- GEMM + argmin over K in 2 tiles of BN=512, double-buffered over (kt,dt) ----
    float best[8];
    int   bi[8];
    #pragma unroll
    for (int r = 0; r < 8; ++r) { best[r] = CUDART_INF_F; bi[r] = 0; }

    for (int kt = 0; kt < KCB / BN; ++kt) {
        unsigned long long acc2[8][8];   // [row][pair]; pair jj -> k = 128*(jj>>1) + tx*4 + (jj&1)*2 (+1)
        #pragma unroll
        for (int r = 0; r < 8; ++r)
            #pragma unroll
            for (int j = 0; j < 8; ++j) acc2[r][j] = 0ULL;

        for (int dt = 0; dt < DDIM / BK; ++dt) {
            const int g = kt * 8 + dt;          // global tile index 0..15
            const int bcur = g & 1;

            // ---- prefetch next tile into the other buffer (overlaps with compute) ----
            if (g < 15) {
                const int gn  = g + 1;
                const int ktn = gn >> 3;
                const int dtn = gn & 7;
                float* dst = cbs + (gn & 1) * CBS_TILE;
                #pragma unroll
                for (int kk = 0; kk < 2; ++kk) {
                    int krow = tid + kk * 256;
                    const float* src = cbg + (size_t)(ktn * BN + krow) * DDIM + dtn * BK;
                    #pragma unroll
                    for (int i = 0; i < 8; ++i) {
                        float4 v = *(const float4*)(src + i * 4);
                        int d = i * 4;
                        dst[(d + 0) * BN + krow] = v.x;
                        dst[(d + 1) * BN + krow] = v.y;
                        dst[(d + 2) * BN + krow] = v.z;
                        dst[(d + 3) * BN + krow] = v.w;
                    }
                }
            }

            // ---- compute current buffer ----
            const unsigned int cbb0 = smb + (unsigned int)((OFF_CBS + bcur * CBS_TILE) * 4) + (unsigned int)(tx * 16);
            #pragma unroll 2
            for (int d = 0; d < BK; ++d) {
                int dg = dt * BK + d;
                // z: two broadcast LDS.128 (warp's 8 rows)
                float4 za = *(const float4*)&zT[dg * ZT_STRIDE + ty * 8];
                float4 zb = *(const float4*)&zT[dg * ZT_STRIDE + ty * 8 + 4];
                // cb: four 128-bit loads straight into packed f32x2 operand regs
                unsigned int cbb = cbb0 + (unsigned int)(d * BN * 4);
                unsigned long long cp[8];
                LDS_PAIR2(cp[0], cp[1], cbb);
                LDS_PAIR2(cp[2], cp[3], cbb + 128 * 4);
                LDS_PAIR2(cp[4], cp[5], cbb + 256 * 4);
                LDS_PAIR2(cp[6], cp[7], cbb + 384 * 4);
                float zr[8] = {za.x, za.y, za.z, za.w, zb.x, zb.y, zb.z, zb.w};
                #pragma unroll
                for (int r = 0; r < 8; ++r) {
                    unsigned long long zd;
                    PACK2(zd, zr[r], zr[r]);
                    #pragma unroll
                    for (int j = 0; j < 8; ++j)
                        FMA2(acc2[r][j], zd, cp[j]);
                }
            }
            __syncthreads();
        }

        // fold distances (reference rounding: (l2 - 2*cl) + c2), ascending k per thread
        #pragma unroll
        for (int r = 0; r < 8; ++r) {
            float l2v = l2s[ty * 8 + r];
            #pragma unroll
            for (int jj = 0; jj < 8; ++jj) {
                unsigned int ulo, uhi;
                UNPACK2(ulo, uhi, acc2[r][jj]);
                float lo = __uint_as_float(ulo);
                float hi = __uint_as_float(uhi);
                int kg = kt * BN + (jj >> 1) * 128 + tx * 4 + (jj & 1) * 2;
                float s0 = (l2v - 2.0f * lo) + c2sh[kg];
                if (s0 < best[r]) { best[r] = s0; bi[r] = kg; }
                float s1 = (l2v - 2.0f * hi) + c2sh[kg + 1];
                if (s1 < best[r]) { best[r] = s1; bi[r] = kg + 1; }
            }
        }
    }

    // ---- cross-thread argmin per row (first-index tie break) ----
    #pragma unroll
    for (int r = 0; r < 8; ++r) {
        int row = ty * 8 + r;
        redS[row * 33 + tx] = best[r];
        redI[row * 33 + tx] = bi[r];
    }
    __syncthreads();
    if (tid < BM) {
        float b  = redS[tid * 33];
        int   ib = redI[tid * 33];
        #pragma unroll
        for (int t = 1; t < 32; ++t) {
            float s  = redS[tid * 33 + t];
            int   i2 = redI[tid * 33 + t];
            if (s < b || (s == b && i2 < ib)) { b = s; ib = i2; }
        }
        bidx[tid] = ib;
    }
    __syncthreads();

    // ---- update: gather code, straight-through fq, residual, loss ----
    double lacc = 0.0;
    #pragma unroll
    for (int it = 0; it < 16; ++it) {
        int f  = tid + it * NTHREADS;
        int m  = f >> 6;
        int d4 = f & 63;
        size_t off = (size_t)(m0 + m) * DDIM + d4 * 4;
        float4 r4 = *(const float4*)(zin + off);
        float4 c4 = *(const float4*)(cbg + (size_t)bidx[m] * DDIM + d4 * 4);
        float4 fo, rn;
        float4 fprev;
        if (!firstStage) fprev = *(const float4*)(fq + off);

        // exact reference rounding chain per element:
        // t = c - r; st = r + t; fq (+)= st; r_next = r - st; loss += t*t
        {
            float t = c4.x - r4.x; float st = r4.x + t;
            fo.x = firstStage ? st : (fprev.x + st); rn.x = r4.x - st;
            lacc += (double)t * (double)t;
        }
        {
            float t = c4.y - r4.y; float st = r4.y + t;
            fo.y = firstStage ? st : (fprev.y + st); rn.y = r4.y - st;
            lacc += (double)t * (double)t;
        }
        {
            float t = c4.z - r4.z; float st = r4.z + t;
            fo.z = firstStage ? st : (fprev.z + st); rn.z = r4.z - st;
            lacc += (double)t * (double)t;
        }
        {
            float t = c4.w - r4.w; float st = r4.w + t;
            fo.w = firstStage ? st : (fprev.w + st); rn.w = r4.w - st;
            lacc += (double)t * (double)t;
        }
        *(float4*)(fq + off) = fo;
        if (writeR) *(float4*)(rout + off) = rn;
    }

    // warp-reduce loss, one atomic per warp
    #pragma unroll
    for (int o = 16; o; o >>= 1) lacc += __shfl_down_sync(0xffffffffu, lacc, o);
    if ((tid & 31) == 0) atomicAdd(lossp, lacc);
}

// ---------------- finalize: write the two (identical) loss scalars ----------------
__global__ void rvq_finalize_kernel(const double* __restrict__ loss, float* __restrict__ out)
{
    if (blockIdx.x == 0 && threadIdx.x == 0) {
        const double nd = (double)((size_t)NROWS * DDIM);
        float L = 0.f;
        for (int i = 0; i < NCB; ++i) L = L + (float)(loss[i] / nd);  // per-stage mean, summed in fp32 like ref
        out[(size_t)NROWS * DDIM]     = L;  // codebook_losses
        out[(size_t)NROWS * DDIM + 1] = L;  // commitment_losses (numerically identical forward)
    }
}

// ---------------- launch ----------------
extern "C" void kernel_launch(void* const* d_in, const int* in_sizes, int n_in,
                              void* d_out, int out_size)
{
    const float* z  = (const float*)d_in[0];   // [65536, 256]
    const float* cb = (const float*)d_in[1];   // [3, 1024, 256]
    float* out = (float*)d_out;

    float*  res_p  = nullptr;
    float*  c2_p   = nullptr;
    double* loss_p = nullptr;
    cudaGetSymbolAddress((void**)&res_p,  g_res);
    cudaGetSymbolAddress((void**)&c2_p,   g_c2);
    cudaGetSymbolAddress((void**)&loss_p, g_loss);

    cudaFuncSetAttribute(rvq_stage_kernel,
                         cudaFuncAttributeMaxDynamicSharedMemorySize, SMEM_BYTES);

    const int nblk = NROWS / BM;  // 1024

    rvq_init_kernel<<<(NCB * KCB * 32) / NTHREADS, NTHREADS>>>(cb, c2_p, loss_p);

    // stage 0: reads z, writes fq (init) + residual
    rvq_stage_kernel<<<nblk, NTHREADS, SMEM_BYTES>>>(
        z, cb, c2_p, out, res_p, loss_p + 0, /*firstStage=*/1, /*writeR=*/1);
    // stage 1: in-place residual (rows block-exclusive, read-before-write)
    rvq_stage_kernel<<<nblk, NTHREADS, SMEM_BYTES>>>(
        res_p, cb + (size_t)KCB * DDIM, c2_p + KCB, out, res_p, loss_p + 1, 0, 1);
    // stage 2: residual output unused -> skip write
    rvq_stage_kernel<<<nblk, NTHREADS, SMEM_BYTES>>>(
        res_p, cb + (size_t)2 * KCB * DDIM, c2_p + 2 * KCB, out, res_p, loss_p + 2, 0, 0);

    rvq_finalize_kernel<<<1, 32>>>(loss_p, out);
}

// round 12
// speedup vs baseline: 1.8004x; 1.8004x over previous
#include <cuda_runtime.h>
#include <math_constants.h>

#define NROWS 65536
#define DDIM  256
#define KCB   1024
#define NCB   3

#define BM 64
#define BN 256
#define BK 16
#define NTHREADS 256
#define CBS_TILE (BK * BN)   // 4096 floats per buffer (16 KB)

// ---------------- scratch (no allocations allowed) ----------------
__device__ float  g_res[(size_t)NROWS * DDIM];       // residual between stages (64 MB)
__device__ float  g_cbT[(size_t)NCB * DDIM * KCB];   // d-major codebooks (3 MB)
__device__ float  g_c2[NCB * KCB];                   // per-stage ||c_k||^2
__device__ double g_loss[NCB];                       // per-stage sum of (code - r)^2

// ---------------- packed f32x2 helpers (sm_103a FFMA2 path) ----------------
#define FMA2(acc, a, b) \
    asm("fma.rn.f32x2 %0, %1, %2, %0;" : "+l"(acc) : "l"(a), "l"(b))
#define PACK2(out, lo, hi) \
    asm("mov.b64 %0, {%1, %2};" : "=l"(out) : "r"(__float_as_uint(lo)), "r"(__float_as_uint(hi)))
#define UNPACK2(lo, hi, in) \
    asm("mov.b64 {%0, %1}, %2;" : "=r"(lo), "=r"(hi) : "l"(in))
// 128-bit smem load directly into two packed f32x2 regs: (k,k+1),(k+2,k+3)
#define LDS_PAIR2(p0, p1, addr) \
    asm("ld.shared.v2.u64 {%0, %1}, [%2];" : "=l"(p0), "=l"(p1) : "r"(addr))
// cp.async 16B gmem->smem (no registers, L1-cached)
#define CP_ASYNC16(saddr, gptr) \
    asm volatile("cp.async.ca.shared.global [%0], [%1], 16;" :: "r"(saddr), "l"(gptr))
#define CP_COMMIT()  asm volatile("cp.async.commit_group;")
#define CP_WAIT0()   asm volatile("cp.async.wait_group 0;")

// ---------------- smem layout (floats) ----------------
// zT   : [256][68]      transposed z tile (d-major, local row index)
// cbs  : [2][16][256]   ping-pong codebook sub-tiles, d-major (cp.async target)
// c2sh : [1024]
// l2s  : [64]
// bidx : [64]
#define ZT_STRIDE 68
#define OFF_ZT    0
#define OFF_CBS   (OFF_ZT  + 256 * ZT_STRIDE)   // 17408
#define OFF_C2    (OFF_CBS + 2 * CBS_TILE)      // 25600
#define OFF_L2    (OFF_C2  + 1024)              // 26624
#define OFF_BIDX  (OFF_L2  + 64)                // 26688
#define SMEM_FLOATS (OFF_BIDX + 64)             // 26752
#define SMEM_BYTES  (SMEM_FLOATS * 4)           // 107008 -> 2 blocks/SM

// ---------------- transpose codebooks to d-major ----------------
__global__ void rvq_transpose_kernel(const float* __restrict__ cb, float* __restrict__ cbT)
{
    int idx = blockIdx.x * blockDim.x + threadIdx.x;   // over NCB*DDIM*KCB
    int s   = idx >> 18;                                // / (DDIM*KCB)
    int rem = idx & ((DDIM * KCB) - 1);
    int d   = rem >> 10;                                // / KCB
    int k   = rem & (KCB - 1);
    cbT[idx] = cb[((size_t)s * KCB + k) * DDIM + d];    // coalesced write, strided read
}

// ---------------- init: zero loss accumulators, compute c2 ----------------
__global__ void rvq_init_kernel(const float* __restrict__ cb,
                                float* __restrict__ c2out,
                                double* __restrict__ loss)
{
    if (blockIdx.x == 0 && threadIdx.x < NCB) loss[threadIdx.x] = 0.0;

    int gw   = (blockIdx.x * blockDim.x + threadIdx.x) >> 5;  // one warp per codeword
    int lane = threadIdx.x & 31;
    if (gw < NCB * KCB) {
        const float* row = cb + (size_t)gw * DDIM;
        float s = 0.f;
        for (int d = lane; d < DDIM; d += 32) { float v = row[d]; s = fmaf(v, v, s); }
        #pragma unroll
        for (int o = 16; o; o >>= 1) s += __shfl_xor_sync(0xffffffffu, s, o);
        if (lane == 0) c2out[gw] = s;
    }
}

// ---------------- fused stage: GEMM + argmin + gather/update/loss ----------------
__global__ __launch_bounds__(NTHREADS, 2)
void rvq_stage_kernel(const float* __restrict__ zin,   // residual input [N,D]
                      const float* __restrict__ cbg,   // codebook rows [K,D] (for gather)
                      const float* __restrict__ cbT,   // codebook d-major [D,K] (for GEMM)
                      const float* __restrict__ c2g,   // stage c2 [K]
                      float* __restrict__ fq,          // output quantized [N,D]
                      float* __restrict__ rout,        // residual output [N,D]
                      double* __restrict__ lossp,      // stage loss accumulator
                      int firstStage, int writeR)
{
    extern __shared__ float sm[];
    float* zT   = sm + OFF_ZT;
    float* c2sh = sm + OFF_C2;
    float* l2s  = sm + OFF_L2;
    int*   bidx = (int*)(sm + OFF_BIDX);

    const unsigned int smb = (unsigned int)__cvta_generic_to_shared(sm);

    const int tid = threadIdx.x;
    const int m0  = blockIdx.x * BM;
    const int tx  = tid & 31;   // lane: local k = tx*4+{0..3} and 128+tx*4+{0..3}
    const int ty  = tid >> 5;   // warp id: owns rows ty*8 .. ty*8+7

    // ---- prologue: start cp.async of cb tile 0 (kt=0, dt=0) into buffer 0 ----
    {
        unsigned int buf = smb + (unsigned int)(OFF_CBS * 4);
        #pragma unroll
        for (int p = 0; p < 4; ++p) {
            int c    = tid + p * NTHREADS;        // 0..1023 (16B chunks)
            int drow = c >> 6;                    // 0..15
            int kc   = (c & 63) << 2;             // 0..252
            CP_ASYNC16(buf + (unsigned int)((drow * BN + kc) * 4),
                       cbT + (size_t)drow * KCB + kc);
        }
        CP_COMMIT();
    }

    // ---- load z tile transposed into smem (coalesced float4 reads) ----
    #pragma unroll
    for (int it = 0; it < 16; ++it) {
        int f  = tid + it * NTHREADS;          // 0..4095
        int m  = f >> 6;                       // row 0..63
        int d4 = f & 63;                       // float4 index along D
        float4 v = *(const float4*)(zin + (size_t)(m0 + m) * DDIM + d4 * 4);
        zT[(d4 * 4 + 0) * ZT_STRIDE + m] = v.x;
        zT[(d4 * 4 + 1) * ZT_STRIDE + m] = v.y;
        zT[(d4 * 4 + 2) * ZT_STRIDE + m] = v.z;
        zT[(d4 * 4 + 3) * ZT_STRIDE + m] = v.w;
    }
    // ---- stage c2 into smem ----
    #pragma unroll
    for (int i = tid; i < KCB; i += NTHREADS) c2sh[i] = c2g[i];
    __syncthreads();

    // ---- l2 per row (same sequential fp32 chain as reference) ----
    if (tid < BM) {
        float s = 0.f;
        for (int d = 0; d < DDIM; ++d) { float v = zT[d * ZT_STRIDE + tid]; s = fmaf(v, v, s); }
        l2s[tid] = s;
    }

    // ---- GEMM + argmin: 64 tiles (kt 0..3 x dt 0..15), cp.async double-buffered ----
    float best[8];
    int   bi[8];
    #pragma unroll
    for (int r = 0; r < 8; ++r) { best[r] = CUDART_INF_F; bi[r] = 0; }

    unsigned long long acc2[8][4];   // [row][pair]; jj -> local k = 128*(jj>>1) + tx*4 + (jj&1)*2 (+1)
    #pragma unroll
    for (int r = 0; r < 8; ++r)
        #pragma unroll
        for (int j = 0; j < 4; ++j) acc2[r][j] = 0ULL;

    for (int g = 0; g < 64; ++g) {
        const int kt = g >> 4;
        const int dt = g & 15;

        // tile g is the only outstanding group -> wait, then barrier for visibility
        CP_WAIT0();
        __syncthreads();

        // prefetch tile g+1 into the other buffer (overlaps with compute below)
        if (g < 63) {
            const int gn  = g + 1;
            const int ktn = gn >> 4;
            const int dtn = gn & 15;
            unsigned int buf = smb + (unsigned int)((OFF_CBS + (gn & 1) * CBS_TILE) * 4);
            const float* src = cbT + (size_t)(dtn * BK) * KCB + ktn * BN;
            #pragma unroll
            for (int p = 0; p < 4; ++p) {
                int c    = tid + p * NTHREADS;
                int drow = c >> 6;
                int kc   = (c & 63) << 2;
                CP_ASYNC16(buf + (unsigned int)((drow * BN + kc) * 4),
                           src + (size_t)drow * KCB + kc);
            }
            CP_COMMIT();
        }

        // ---- compute current buffer: 16 d-steps ----
        const unsigned int cbb0 = smb + (unsigned int)((OFF_CBS + (g & 1) * CBS_TILE) * 4)
                                      + (unsigned int)(tx * 16);
        #pragma unroll
        for (int d = 0; d < BK; ++d) {
            int dg = dt * BK + d;
            // z: two broadcast LDS.128 (warp's 8 rows)
            float4 za = *(const float4*)&zT[dg * ZT_STRIDE + ty * 8];
            float4 zb = *(const float4*)&zT[dg * ZT_STRIDE + ty * 8 + 4];
            // cb: two 128-bit loads straight into packed f32x2 operand regs
            unsigned int cbb = cbb0 + (unsigned int)(d * BN * 4);
            unsigned long long cp[4];
            LDS_PAIR2(cp[0], cp[1], cbb);
            LDS_PAIR2(cp[2], cp[3], cbb + 128 * 4);
            float zr[8] = {za.x, za.y, za.z, za.w, zb.x, zb.y, zb.z, zb.w};
            #pragma unroll
            for (int r = 0; r < 8; ++r) {
                unsigned long long zd;
                PACK2(zd, zr[r], zr[r]);
                #pragma unroll
                for (int j = 0; j < 4; ++j)
                    FMA2(acc2[r][j], zd, cp[j]);
            }
        }

        // ---- end of kt: fold distances, reset accumulators ----
        if (dt == 15) {
            #pragma unroll
            for (int r = 0; r < 8; ++r) {
                float l2v = l2s[ty * 8 + r];
                #pragma unroll
                for (int jj = 0; jj < 4; ++jj) {
                    unsigned int ulo, uhi;
                    UNPACK2(ulo, uhi, acc2[r][jj]);
                    float lo = __uint_as_float(ulo);
                    float hi = __uint_as_float(uhi);
                    int kg = kt * BN + (jj >> 1) * 128 + tx * 4 + (jj & 1) * 2;
                    float s0 = (l2v - 2.0f * lo) + c2sh[kg];
                    if (s0 < best[r]) { best[r] = s0; bi[r] = kg; }
                    float s1 = (l2v - 2.0f * hi) + c2sh[kg + 1];
                    if (s1 < best[r]) { best[r] = s1; bi[r] = kg + 1; }
                    acc2[r][jj] = 0ULL;
                }
            }
        }
    }

    // ---- cross-lane argmin per row (min value, then min index) via shfl ----
    #pragma unroll
    for (int r = 0; r < 8; ++r) {
        float b  = best[r];
        int   ib = bi[r];
        #pragma unroll
        for (int o = 16; o; o >>= 1) {
            float s  = __shfl_xor_sync(0xffffffffu, b,  o);
            int   i2 = __shfl_xor_sync(0xffffffffu, ib, o);
            if (s < b || (s == b && i2 < ib)) { b = s; ib = i2; }
        }
        if (tx == 0) bidx[ty * 8 + r] = ib;
    }
    __syncthreads();

    // ---- update: gather code, straight-through fq, residual, loss ----
    double lacc = 0.0;
    #pragma unroll
    for (int it = 0; it < 16; ++it) {
        int f  = tid + it * NTHREADS;
        int m  = f >> 6;
        int d4 = f & 63;
        size_t off = (size_t)(m0 + m) * DDIM + d4 * 4;
        float4 r4 = *(const float4*)(zin + off);
        float4 c4 = *(const float4*)(cbg + (size_t)bidx[m] * DDIM + d4 * 4);
        float4 fo, rn;
        float4 fprev;
        if (!firstStage) fprev = *(const float4*)(fq + off);

        // exact reference rounding chain per element:
        // t = c - r; st = r + t; fq (+)= st; r_next = r - st; loss += t*t
        {
            float t = c4.x - r4.x; float st = r4.x + t;
            fo.x = firstStage ? st : (fprev.x + st); rn.x = r4.x - st;
            lacc += (double)t * (double)t;
        }
        {
            float t = c4.y - r4.y; float st = r4.y + t;
            fo.y = firstStage ? st : (fprev.y + st); rn.y = r4.y - st;
            lacc += (double)t * (double)t;
        }
        {
            float t = c4.z - r4.z; float st = r4.z + t;
            fo.z = firstStage ? st : (fprev.z + st); rn.z = r4.z - st;
            lacc += (double)t * (double)t;
        }
        {
            float t = c4.w - r4.w; float st = r4.w + t;
            fo.w = firstStage ? st : (fprev.w + st); rn.w = r4.w - st;
            lacc += (double)t * (double)t;
        }
        *(float4*)(fq + off) = fo;
        if (writeR) *(float4*)(rout + off) = rn;
    }

    // warp-reduce loss, one atomic per warp
    #pragma unroll
    for (int o = 16; o; o >>= 1) lacc += __shfl_down_sync(0xffffffffu, lacc, o);
    if ((tid & 31) == 0) atomicAdd(lossp, lacc);
}

// ---------------- finalize: write the two (identical) loss scalars ----------------
__global__ void rvq_finalize_kernel(const double* __restrict__ loss, float* __restrict__ out)
{
    if (blockIdx.x == 0 && threadIdx.x == 0) {
        const double nd = (double)((size_t)NROWS * DDIM);
        float L = 0.f;
        for (int i = 0; i < NCB; ++i) L = L + (float)(loss[i] / nd);  // per-stage mean, summed in fp32 like ref
        out[(size_t)NROWS * DDIM]     = L;  // codebook_losses
        out[(size_t)NROWS * DDIM + 1] = L;  // commitment_losses (numerically identical forward)
    }
}

// ---------------- launch ----------------
extern "C" void kernel_launch(void* const* d_in, const int* in_sizes, int n_in,
                              void* d_out, int out_size)
{
    const float* z  = (const float*)d_in[0];   // [65536, 256]
    const float* cb = (const float*)d_in[1];   // [3, 1024, 256]
    float* out = (float*)d_out;

    float*  res_p  = nullptr;
    float*  cbT_p  = nullptr;
    float*  c2_p   = nullptr;
    double* loss_p = nullptr;
    cudaGetSymbolAddress((void**)&res_p,  g_res);
    cudaGetSymbolAddress((void**)&cbT_p,  g_cbT);
    cudaGetSymbolAddress((void**)&c2_p,   g_c2);
    cudaGetSymbolAddress((void**)&loss_p, g_loss);

    cudaFuncSetAttribute(rvq_stage_kernel,
                         cudaFuncAttributeMaxDynamicSharedMemorySize, SMEM_BYTES);

    const int nblk = NROWS / BM;  // 1024

    rvq_init_kernel<<<(NCB * KCB * 32) / NTHREADS, NTHREADS>>>(cb, c2_p, loss_p);
    rvq_transpose_kernel<<<(NCB * DDIM * KCB) / NTHREADS, NTHREADS>>>(cb, cbT_p);

    // stage 0: reads z, writes fq (init) + residual
    rvq_stage_kernel<<<nblk, NTHREADS, SMEM_BYTES>>>(
        z, cb, cbT_p, c2_p, out, res_p, loss_p + 0, /*firstStage=*/1, /*writeR=*/1);
    // stage 1: in-place residual (rows block-exclusive, read-before-write)
    rvq_stage_kernel<<<nblk, NTHREADS, SMEM_BYTES>>>(
        res_p, cb + (size_t)KCB * DDIM, cbT_p + (size_t)DDIM * KCB, c2_p + KCB,
        out, res_p, loss_p + 1, 0, 1);
    // stage 2: residual output unused -> skip write
    rvq_stage_kernel<<<nblk, NTHREADS, SMEM_BYTES>>>(
        res_p, cb + (size_t)2 * KCB * DDIM, cbT_p + (size_t)2 * DDIM * KCB, c2_p + 2 * KCB,
        out, res_p, loss_p + 2, 0, 0);

    rvq_finalize_kernel<<<1, 32>>>(loss_p, out);
}

// round 13
// speedup vs baseline: 1.8331x; 1.0182x over previous
#include <cuda_runtime.h>
#include <math_constants.h>

#define NROWS 65536
#define DDIM  256
#define KCB   1024
#define NCB   3

#define BM 64
#define BN 256
#define BK 16
#define NTHREADS 256
#define CBS_TILE (BK * BN)   // 4096 floats per buffer (16 KB)

// ---------------- scratch (no allocations allowed) ----------------
__device__ float  g_res[(size_t)NROWS * DDIM];       // residual between stages (64 MB)
__device__ float  g_cbT[(size_t)NCB * DDIM * KCB];   // d-major codebooks (3 MB)
__device__ float  g_c2[NCB * KCB];                   // per-stage ||c_k||^2
__device__ double g_loss[NCB];                       // per-stage sum of (code - r)^2

// ---------------- packed f32x2 helpers (sm_103a FFMA2 path) ----------------
#define FMA2(acc, a, b) \
    asm("fma.rn.f32x2 %0, %1, %2, %0;" : "+l"(acc) : "l"(a), "l"(b))
#define PACK2(out, lo, hi) \
    asm("mov.b64 %0, {%1, %2};" : "=l"(out) : "r"(__float_as_uint(lo)), "r"(__float_as_uint(hi)))
#define UNPACK2(lo, hi, in) \
    asm("mov.b64 {%0, %1}, %2;" : "=r"(lo), "=r"(hi) : "l"(in))
// 128-bit smem load directly into two packed f32x2 regs: (k,k+1),(k+2,k+3)
#define LDS_PAIR2(p0, p1, addr) \
    asm("ld.shared.v2.u64 {%0, %1}, [%2];" : "=l"(p0), "=l"(p1) : "r"(addr))
// cp.async 16B gmem->smem (no registers, L1-cached)
#define CP_ASYNC16(saddr, gptr) \
    asm volatile("cp.async.ca.shared.global [%0], [%1], 16;" :: "r"(saddr), "l"(gptr))
#define CP_COMMIT()  asm volatile("cp.async.commit_group;")
#define CP_WAIT0()   asm volatile("cp.async.wait_group 0;")

// ---------------- smem layout (floats) ----------------
// zT    : [4][64][68]   z tile planes: value for (d, m) at plane d&3, row d>>2, col m
//                       (store: lanes span d4 -> bank stride 68 -> 4-way max conflict;
//                        compute: float4 over m at fixed d -> aligned, broadcast)
// cbs   : [2][16][256]  ping-pong codebook sub-tiles, d-major (cp.async target)
// c2sh  : [1024]
// l2s   : [64]
// bestR : [64]  running per-row best distance (merged per kt by row-owner warp lane0)
// idxR  : [64]  running per-row best index
#define ZT_PLANE  (64 * 68)                     // 4352 floats per plane
#define OFF_ZT    0
#define OFF_CBS   (OFF_ZT  + 4 * ZT_PLANE)      // 17408
#define OFF_C2    (OFF_CBS + 2 * CBS_TILE)      // 25600
#define OFF_L2    (OFF_C2  + 1024)              // 26624
#define OFF_BESTR (OFF_L2  + 64)                // 26688
#define OFF_IDXR  (OFF_BESTR + 64)              // 26752
#define SMEM_FLOATS (OFF_IDXR + 64)             // 26816
#define SMEM_BYTES  (SMEM_FLOATS * 4)           // 107264 -> 2 blocks/SM

// ---------------- transpose codebooks to d-major ----------------
__global__ void rvq_transpose_kernel(const float* __restrict__ cb, float* __restrict__ cbT)
{
    int idx = blockIdx.x * blockDim.x + threadIdx.x;   // over NCB*DDIM*KCB
    int s   = idx >> 18;                                // / (DDIM*KCB)
    int rem = idx & ((DDIM * KCB) - 1);
    int d   = rem >> 10;                                // / KCB
    int k   = rem & (KCB - 1);
    cbT[idx] = cb[((size_t)s * KCB + k) * DDIM + d];    // coalesced write, strided read
}

// ---------------- init: zero loss accumulators, compute c2 ----------------
__global__ void rvq_init_kernel(const float* __restrict__ cb,
                                float* __restrict__ c2out,
                                double* __restrict__ loss)
{
    if (blockIdx.x == 0 && threadIdx.x < NCB) loss[threadIdx.x] = 0.0;

    int gw   = (blockIdx.x * blockDim.x + threadIdx.x) >> 5;  // one warp per codeword
    int lane = threadIdx.x & 31;
    if (gw < NCB * KCB) {
        const float* row = cb + (size_t)gw * DDIM;
        float s = 0.f;
        for (int d = lane; d < DDIM; d += 32) { float v = row[d]; s = fmaf(v, v, s); }
        #pragma unroll
        for (int o = 16; o; o >>= 1) s += __shfl_xor_sync(0xffffffffu, s, o);
        if (lane == 0) c2out[gw] = s;
    }
}

// ---------------- fused stage: GEMM + argmin + gather/update/loss ----------------
__global__ __launch_bounds__(NTHREADS, 2)
void rvq_stage_kernel(const float* __restrict__ zin,   // residual input [N,D]
                      const float* __restrict__ cbg,   // codebook rows [K,D] (for gather)
                      const float* __restrict__ cbT,   // codebook d-major [D,K] (for GEMM)
                      const float* __restrict__ c2g,   // stage c2 [K]
                      float* __restrict__ fq,          // output quantized [N,D]
                      float* __restrict__ rout,        // residual output [N,D]
                      double* __restrict__ lossp,      // stage loss accumulator
                      int firstStage, int writeR)
{
    extern __shared__ float sm[];
    float* zT    = sm + OFF_ZT;
    float* c2sh  = sm + OFF_C2;
    float* l2s   = sm + OFF_L2;
    float* bestR = sm + OFF_BESTR;
    int*   idxR  = (int*)(sm + OFF_IDXR);

    const unsigned int smb = (unsigned int)__cvta_generic_to_shared(sm);

    const int tid = threadIdx.x;
    const int m0  = blockIdx.x * BM;
    const int tx  = tid & 31;   // lane: local k = tx*4+{0..3} and 128+tx*4+{0..3}
    const int ty  = tid >> 5;   // warp id: owns rows ty*8 .. ty*8+7

    // ---- prologue: start cp.async of cb tile 0 (kt=0, dt=0) into buffer 0 ----
    {
        unsigned int buf = smb + (unsigned int)(OFF_CBS * 4);
        #pragma unroll
        for (int p = 0; p < 4; ++p) {
            int c    = tid + p * NTHREADS;        // 0..1023 (16B chunks)
            int drow = c >> 6;                    // 0..15
            int kc   = (c & 63) << 2;             // 0..252
            CP_ASYNC16(buf + (unsigned int)((drow * BN + kc) * 4),
                       cbT + (size_t)drow * KCB + kc);
        }
        CP_COMMIT();
    }

    // ---- load z tile into planed smem (coalesced float4 reads, 4-way max STS) ----
    #pragma unroll
    for (int it = 0; it < 16; ++it) {
        int f  = tid + it * NTHREADS;          // 0..4095
        int m  = f >> 6;                       // row 0..63
        int d4 = f & 63;                       // float4 index along D (d = d4*4+c)
        float4 v = *(const float4*)(zin + (size_t)(m0 + m) * DDIM + d4 * 4);
        // d = 4*d4 + c -> plane c, plane-row d4, col m
        zT[0 * ZT_PLANE + d4 * 68 + m] = v.x;
        zT[1 * ZT_PLANE + d4 * 68 + m] = v.y;
        zT[2 * ZT_PLANE + d4 * 68 + m] = v.z;
        zT[3 * ZT_PLANE + d4 * 68 + m] = v.w;
    }
    // ---- stage c2 into smem ----
    #pragma unroll
    for (int i = tid; i < KCB; i += NTHREADS) c2sh[i] = c2g[i];
    // ---- init running argmin ----
    if (tid < BM) { bestR[tid] = CUDART_INF_F; idxR[tid] = 0; }
    __syncthreads();

    // ---- l2 per row (same sequential fp32 chain as reference) ----
    if (tid < BM) {
        float s = 0.f;
        for (int d = 0; d < DDIM; ++d) {
            float v = zT[(d & 3) * ZT_PLANE + (d >> 2) * 68 + tid];
            s = fmaf(v, v, s);
        }
        l2s[tid] = s;
    }

    // ---- GEMM + argmin: 64 tiles (kt 0..3 x dt 0..15), cp.async double-buffered ----
    unsigned long long acc2[8][4];   // [row][pair]; jj -> local k = 128*(jj>>1) + tx*4 + (jj&1)*2 (+1)
    #pragma unroll
    for (int r = 0; r < 8; ++r)
        #pragma unroll
        for (int j = 0; j < 4; ++j) acc2[r][j] = 0ULL;

    for (int g = 0; g < 64; ++g) {
        const int kt = g >> 4;
        const int dt = g & 15;

        // tile g is the only outstanding group -> wait, then barrier for visibility
        CP_WAIT0();
        __syncthreads();

        // prefetch tile g+1 into the other buffer (overlaps with compute below)
        if (g < 63) {
            const int gn  = g + 1;
            const int ktn = gn >> 4;
            const int dtn = gn & 15;
            unsigned int buf = smb + (unsigned int)((OFF_CBS + (gn & 1) * CBS_TILE) * 4);
            const float* src = cbT + (size_t)(dtn * BK) * KCB + ktn * BN;
            #pragma unroll
            for (int p = 0; p < 4; ++p) {
                int c    = tid + p * NTHREADS;
                int drow = c >> 6;
                int kc   = (c & 63) << 2;
                CP_ASYNC16(buf + (unsigned int)((drow * BN + kc) * 4),
                           src + (size_t)drow * KCB + kc);
            }
            CP_COMMIT();
        }

        // ---- compute current buffer: 16 d-steps ----
        const unsigned int cbb0 = smb + (unsigned int)((OFF_CBS + (g & 1) * CBS_TILE) * 4)
                                      + (unsigned int)(tx * 16);
        #pragma unroll
        for (int d = 0; d < BK; ++d) {
            int dg = dt * BK + d;              // dg&3 = d&3 ; dg>>2 = dt*4 + (d>>2)
            // cb first: two 128-bit loads straight into packed f32x2 operand regs
            unsigned int cbb = cbb0 + (unsigned int)(d * BN * 4);
            unsigned long long cp[4];
            LDS_PAIR2(cp[0], cp[1], cbb);
            LDS_PAIR2(cp[2], cp[3], cbb + 128 * 4);
            // z: two broadcast LDS.128 (warp's 8 rows) from plane layout
            const float* zrow = &zT[(d & 3) * ZT_PLANE + (dt * 4 + (d >> 2)) * 68 + ty * 8];
            float4 za = *(const float4*)zrow;
            float4 zb = *(const float4*)(zrow + 4);
            float zr[8] = {za.x, za.y, za.z, za.w, zb.x, zb.y, zb.z, zb.w};
            #pragma unroll
            for (int r = 0; r < 8; ++r) {
                unsigned long long zd;
                PACK2(zd, zr[r], zr[r]);
                #pragma unroll
                for (int j = 0; j < 4; ++j)
                    FMA2(acc2[r][j], zd, cp[j]);
            }
        }

        // ---- end of kt: fold distances, shfl-reduce, merge into smem, reset accs ----
        if (dt == 15) {
            #pragma unroll
            for (int r = 0; r < 8; ++r) {
                float l2v = l2s[ty * 8 + r];
                float b   = CUDART_INF_F;
                int   ib  = 0;
                #pragma unroll
                for (int jj = 0; jj < 4; ++jj) {
                    unsigned int ulo, uhi;
                    UNPACK2(ulo, uhi, acc2[r][jj]);
                    float lo = __uint_as_float(ulo);
                    float hi = __uint_as_float(uhi);
                    int kg = kt * BN + (jj >> 1) * 128 + tx * 4 + (jj & 1) * 2;
                    float s0 = (l2v - 2.0f * lo) + c2sh[kg];
                    if (s0 < b) { b = s0; ib = kg; }
                    float s1 = (l2v - 2.0f * hi) + c2sh[kg + 1];
                    if (s1 < b) { b = s1; ib = kg + 1; }
                    acc2[r][jj] = 0ULL;
                }
                // cross-lane reduce (min value, min index on tie)
                #pragma unroll
                for (int o = 16; o; o >>= 1) {
                    float s  = __shfl_xor_sync(0xffffffffu, b,  o);
                    int   i2 = __shfl_xor_sync(0xffffffffu, ib, o);
                    if (s < b || (s == b && i2 < ib)) { b = s; ib = i2; }
                }
                // lane 0 merges into the running per-row best (rows owned by this warp only;
                // kt ascending + strict < keeps the reference first-index tie-break)
                if (tx == 0) {
                    int row = ty * 8 + r;
                    if (b < bestR[row]) { bestR[row] = b; idxR[row] = ib; }
                }
            }
        }
    }
    __syncthreads();

    // ---- update: gather code, straight-through fq, residual, loss ----
    double lacc = 0.0;
    #pragma unroll
    for (int it = 0; it < 16; ++it) {
        int f  = tid + it * NTHREADS;
        int m  = f >> 6;
        int d4 = f & 63;
        size_t off = (size_t)(m0 + m) * DDIM + d4 * 4;
        float4 r4 = *(const float4*)(zin + off);
        float4 c4 = *(const float4*)(cbg + (size_t)idxR[m] * DDIM + d4 * 4);
        float4 fo, rn;
        float4 fprev;
        if (!firstStage) fprev = *(const float4*)(fq + off);

        // exact reference rounding chain per element:
        // t = c - r; st = r + t; fq (+)= st; r_next = r - st; loss += t*t
        {
            float t = c4.x - r4.x; float st = r4.x + t;
            fo.x = firstStage ? st : (fprev.x + st); rn.x = r4.x - st;
            lacc += (double)t * (double)t;
        }
        {
            float t = c4.y - r4.y; float st = r4.y + t;
            fo.y = firstStage ? st : (fprev.y + st); rn.y = r4.y - st;
            lacc += (double)t * (double)t;
        }
        {
            float t = c4.z - r4.z; float st = r4.z + t;
            fo.z = firstStage ? st : (fprev.z + st); rn.z = r4.z - st;
            lacc += (double)t * (double)t;
        }
        {
            float t = c4.w - r4.w; float st = r4.w + t;
            fo.w = firstStage ? st : (fprev.w + st); rn.w = r4.w - st;
            lacc += (double)t * (double)t;
        }
        *(float4*)(fq + off) = fo;
        if (writeR) *(float4*)(rout + off) = rn;
    }

    // warp-reduce loss, one atomic per warp
    #pragma unroll
    for (int o = 16; o; o >>= 1) lacc += __shfl_down_sync(0xffffffffu, lacc, o);
    if ((tid & 31) == 0) atomicAdd(lossp, lacc);
}

// ---------------- finalize: write the two (identical) loss scalars ----------------
__global__ void rvq_finalize_kernel(const double* __restrict__ loss, float* __restrict__ out)
{
    if (blockIdx.x == 0 && threadIdx.x == 0) {
        const double nd = (double)((size_t)NROWS * DDIM);
        float L = 0.f;
        for (int i = 0; i < NCB; ++i) L = L + (float)(loss[i] / nd);  // per-stage mean, summed in fp32 like ref
        out[(size_t)NROWS * DDIM]     = L;  // codebook_losses
        out[(size_t)NROWS * DDIM + 1] = L;  // commitment_losses (numerically identical forward)
    }
}

// ---------------- launch ----------------
extern "C" void kernel_launch(void* const* d_in, const int* in_sizes, int n_in,
                              void* d_out, int out_size)
{
    const float* z  = (const float*)d_in[0];   // [65536, 256]
    const float* cb = (const float*)d_in[1];   // [3, 1024, 256]
    float* out = (float*)d_out;

    float*  res_p  = nullptr;
    float*  cbT_p  = nullptr;
    float*  c2_p   = nullptr;
    double* loss_p = nullptr;
    cudaGetSymbolAddress((void**)&res_p,  g_res);
    cudaGetSymbolAddress((void**)&cbT_p,  g_cbT);
    cudaGetSymbolAddress((void**)&c2_p,   g_c2);
    cudaGetSymbolAddress((void**)&loss_p, g_loss);

    cudaFuncSetAttribute(rvq_stage_kernel,
                         cudaFuncAttributeMaxDynamicSharedMemorySize, SMEM_BYTES);

    const int nblk = NROWS / BM;  // 1024

    rvq_init_kernel<<<(NCB * KCB * 32) / NTHREADS, NTHREADS>>>(cb, c2_p, loss_p);
    rvq_transpose_kernel<<<(NCB * DDIM * KCB) / NTHREADS, NTHREADS>>>(cb, cbT_p);

    // stage 0: reads z, writes fq (init) + residual
    rvq_stage_kernel<<<nblk, NTHREADS, SMEM_BYTES>>>(
        z, cb, cbT_p, c2_p, out, res_p, loss_p + 0, /*firstStage=*/1, /*writeR=*/1);
    // stage 1: in-place residual (rows block-exclusive, read-before-write)
    rvq_stage_kernel<<<nblk, NTHREADS, SMEM_BYTES>>>(
        res_p, cb + (size_t)KCB * DDIM, cbT_p + (size_t)DDIM * KCB, c2_p + KCB,
        out, res_p, loss_p + 1, 0, 1);
    // stage 2: residual output unused -> skip write
    rvq_stage_kernel<<<nblk, NTHREADS, SMEM_BYTES>>>(
        res_p, cb + (size_t)2 * KCB * DDIM, cbT_p + (size_t)2 * DDIM * KCB, c2_p + 2 * KCB,
        out, res_p, loss_p + 2, 0, 0);

    rvq_finalize_kernel<<<1, 32>>>(loss_p, out);
}